// round 1
// baseline (speedup 1.0000x reference)
#include <cuda_runtime.h>
#include <math.h>

#define D_MODEL 1024
#define SEQ     2048
#define NB      2
#define NH      16
#define HD      64
#define BHS     (NB*NH)

// Scratch (static device globals — no allocation at runtime)
__device__ float g_Q[(size_t)BHS * SEQ * HD];
__device__ float g_K[(size_t)BHS * SEQ * HD];
__device__ float g_V[(size_t)BHS * SEQ * HD];
__device__ float g_AO[(size_t)NB * SEQ * D_MODEL];

// ---------------------------------------------------------------------------
// GEMM: out = X @ W^T + bias.   X: (M,1024) row-major, W: (1024,1024) row-major.
// toBHSD=1: scatter into (B,H,S,Hd) layout (for Q/K/V). Otherwise plain (M,N).
// 64x64 tile, K-step 32, 128 threads, 4x8 microtile per thread.
// ---------------------------------------------------------------------------
__global__ __launch_bounds__(128) void gemm_bias(const float* __restrict__ X,
                                                 const float* __restrict__ W,
                                                 const float* __restrict__ bias,
                                                 float* __restrict__ out,
                                                 int toBHSD)
{
    __shared__ float Xs[32][68];   // [k][m], padded (68*4B = 16B aligned, stride%32=4)
    __shared__ float Ws[32][68];   // [k][n]

    const int bm  = blockIdx.y * 64;
    const int bn  = blockIdx.x * 64;
    const int tid = threadIdx.x;
    const int tx  = tid & 7;       // 8 col-groups of 8
    const int ty  = tid >> 3;      // 16 row-groups of 4

    float acc[4][8];
#pragma unroll
    for (int i = 0; i < 4; i++)
#pragma unroll
        for (int j = 0; j < 8; j++) acc[i][j] = 0.f;

    for (int k0 = 0; k0 < D_MODEL; k0 += 32) {
#pragma unroll
        for (int i = 0; i < 4; i++) {
            int li = tid + i * 128;        // 0..511 (64 rows * 8 float4)
            int r  = li >> 3;
            int c4 = (li & 7) * 4;
            float4 v = *(const float4*)(X + (size_t)(bm + r) * D_MODEL + k0 + c4);
            Xs[c4 + 0][r] = v.x; Xs[c4 + 1][r] = v.y;
            Xs[c4 + 2][r] = v.z; Xs[c4 + 3][r] = v.w;
            float4 w = *(const float4*)(W + (size_t)(bn + r) * D_MODEL + k0 + c4);
            Ws[c4 + 0][r] = w.x; Ws[c4 + 1][r] = w.y;
            Ws[c4 + 2][r] = w.z; Ws[c4 + 3][r] = w.w;
        }
        __syncthreads();
#pragma unroll
        for (int kk = 0; kk < 32; kk++) {
            float4 a  = *(const float4*)&Xs[kk][ty * 4];
            float4 b0 = *(const float4*)&Ws[kk][tx * 8];
            float4 b1 = *(const float4*)&Ws[kk][tx * 8 + 4];
            float av[4] = {a.x, a.y, a.z, a.w};
            float bv[8] = {b0.x, b0.y, b0.z, b0.w, b1.x, b1.y, b1.z, b1.w};
#pragma unroll
            for (int i = 0; i < 4; i++)
#pragma unroll
                for (int j = 0; j < 8; j++)
                    acc[i][j] = fmaf(av[i], bv[j], acc[i][j]);
        }
        __syncthreads();
    }

#pragma unroll
    for (int i = 0; i < 4; i++) {
        int m = bm + ty * 4 + i;
#pragma unroll
        for (int j = 0; j < 8; j++) {
            int n = bn + tx * 8 + j;
            float v = acc[i][j] + bias[n];
            if (toBHSD) {
                int b = m >> 11, s = m & (SEQ - 1);
                int h = n >> 6,  d = n & (HD - 1);
                out[(((size_t)(b * NH + h)) * SEQ + s) * HD + d] = v;
            } else {
                out[(size_t)m * D_MODEL + n] = v;
            }
        }
    }
}

// ---------------------------------------------------------------------------
// Flash attention: per block = one (b,h) x 64-query tile, streaming 32-key tiles.
// Online softmax with row stats held redundantly in registers across the 8 lanes
// that share each row group (no shared-mem stats, no cross-warp sync for softmax).
// ---------------------------------------------------------------------------
__global__ __launch_bounds__(128) void attn_kernel()
{
    __shared__ float Qs[HD][64 + 4];   // [d][q]  17.4 KB
    __shared__ float Ks[HD][32 + 4];   // [d][k]   9.2 KB
    __shared__ float Vs[32][HD + 4];   // [k][d]   8.7 KB
    __shared__ float Ps[32][64 + 4];   // [k][q]   8.7 KB

    const int bh    = blockIdx.y;
    const int qbase = blockIdx.x * 64;
    const float* Qg = g_Q + (size_t)bh * SEQ * HD;
    const float* Kg = g_K + (size_t)bh * SEQ * HD;
    const float* Vg = g_V + (size_t)bh * SEQ * HD;

    const int tid = threadIdx.x;
    const int tx  = tid & 7;
    const int ty  = tid >> 3;
    const float SCALE = 0.125f;  // 1/sqrt(64)

    // Load Q tile (64x64) transposed + pre-scaled
#pragma unroll
    for (int i = 0; i < 8; i++) {
        int li = tid + i * 128;        // 0..1023 float4s
        int r  = li >> 4;
        int c4 = (li & 15) * 4;
        float4 v = *(const float4*)(Qg + (size_t)(qbase + r) * HD + c4);
        Qs[c4 + 0][r] = v.x * SCALE; Qs[c4 + 1][r] = v.y * SCALE;
        Qs[c4 + 2][r] = v.z * SCALE; Qs[c4 + 3][r] = v.w * SCALE;
    }

    float o[4][8];
    float m_r[4], l_r[4];
#pragma unroll
    for (int i = 0; i < 4; i++) {
        m_r[i] = -INFINITY; l_r[i] = 0.f;
#pragma unroll
        for (int j = 0; j < 8; j++) o[i][j] = 0.f;
    }

    for (int kt = 0; kt < SEQ; kt += 32) {
        __syncthreads();   // previous PV reads of Vs/Ps done before overwrite
#pragma unroll
        for (int i = 0; i < 4; i++) {
            int li = tid + i * 128;    // 0..511 (32 rows * 16 float4)
            int r  = li >> 4;
            int c4 = (li & 15) * 4;
            float4 v = *(const float4*)(Kg + (size_t)(kt + r) * HD + c4);
            Ks[c4 + 0][r] = v.x; Ks[c4 + 1][r] = v.y;
            Ks[c4 + 2][r] = v.z; Ks[c4 + 3][r] = v.w;
            float4 w = *(const float4*)(Vg + (size_t)(kt + r) * HD + c4);
            *(float4*)&Vs[r][c4] = w;
        }
        __syncthreads();

        // S = Q @ K^T : thread tile 4 q-rows (ty*4+i) x 4 k-cols (tx*4+j)
        float sc[4][4];
#pragma unroll
        for (int i = 0; i < 4; i++)
#pragma unroll
            for (int j = 0; j < 4; j++) sc[i][j] = 0.f;
#pragma unroll 16
        for (int kk = 0; kk < HD; kk++) {
            float4 a = *(const float4*)&Qs[kk][ty * 4];
            float4 b = *(const float4*)&Ks[kk][tx * 4];
            float av[4] = {a.x, a.y, a.z, a.w};
            float bv[4] = {b.x, b.y, b.z, b.w};
#pragma unroll
            for (int i = 0; i < 4; i++)
#pragma unroll
                for (int j = 0; j < 4; j++)
                    sc[i][j] = fmaf(av[i], bv[j], sc[i][j]);
        }

        // Online softmax: rows shared by 8 lanes (same ty), reduce via shfl.
#pragma unroll
        for (int i = 0; i < 4; i++) {
            float mx = fmaxf(fmaxf(sc[i][0], sc[i][1]), fmaxf(sc[i][2], sc[i][3]));
#pragma unroll
            for (int ofs = 1; ofs < 8; ofs <<= 1)
                mx = fmaxf(mx, __shfl_xor_sync(0xffffffffu, mx, ofs));
            float m_new = fmaxf(m_r[i], mx);
            float p[4], ts = 0.f;
#pragma unroll
            for (int j = 0; j < 4; j++) { p[j] = __expf(sc[i][j] - m_new); ts += p[j]; }
#pragma unroll
            for (int ofs = 1; ofs < 8; ofs <<= 1)
                ts += __shfl_xor_sync(0xffffffffu, ts, ofs);
            float alpha = __expf(m_r[i] - m_new);   // first tile: exp(-inf)=0
            l_r[i] = l_r[i] * alpha + ts;
            m_r[i] = m_new;
            int r = ty * 4 + i;
#pragma unroll
            for (int j = 0; j < 4; j++) Ps[tx * 4 + j][r] = p[j];
#pragma unroll
            for (int j = 0; j < 8; j++) o[i][j] *= alpha;
        }
        __syncwarp();   // Ps is warp-local; order writes before PV reads

        // O += P @ V : thread tile 4 q-rows x 8 dims (tx*8+j)
#pragma unroll
        for (int kk = 0; kk < 32; kk++) {
            float4 a  = *(const float4*)&Ps[kk][ty * 4];
            float4 b0 = *(const float4*)&Vs[kk][tx * 8];
            float4 b1 = *(const float4*)&Vs[kk][tx * 8 + 4];
            float av[4] = {a.x, a.y, a.z, a.w};
            float bv[8] = {b0.x, b0.y, b0.z, b0.w, b1.x, b1.y, b1.z, b1.w};
#pragma unroll
            for (int i = 0; i < 4; i++)
#pragma unroll
                for (int j = 0; j < 8; j++)
                    o[i][j] = fmaf(av[i], bv[j], o[i][j]);
        }
    }

    // Finalize: divide by l, write (B,S,H,Hd) == (B,S,D) layout for the O-proj GEMM
    const int b = bh >> 4, h = bh & 15;
#pragma unroll
    for (int i = 0; i < 4; i++) {
        int s = qbase + ty * 4 + i;
        float inv = 1.f / l_r[i];
        float* dst = g_AO + ((size_t)b * SEQ + s) * D_MODEL + h * HD + tx * 8;
#pragma unroll
        for (int j = 0; j < 8; j++) dst[j] = o[i][j] * inv;
    }
}

// ---------------------------------------------------------------------------
extern "C" void kernel_launch(void* const* d_in, const int* in_sizes, int n_in,
                              void* d_out, int out_size)
{
    const float* query = (const float*)d_in[0];
    const float* key   = (const float*)d_in[1];
    const float* value = (const float*)d_in[2];
    const float* Wq    = (const float*)d_in[3];
    const float* bq    = (const float*)d_in[4];
    const float* Wk    = (const float*)d_in[5];
    const float* bk    = (const float*)d_in[6];
    const float* Wv    = (const float*)d_in[7];
    const float* bv    = (const float*)d_in[8];
    const float* Wo    = (const float*)d_in[9];
    const float* bo    = (const float*)d_in[10];
    float* out = (float*)d_out;

    float *Qp, *Kp, *Vp, *AOp;
    cudaGetSymbolAddress((void**)&Qp,  g_Q);
    cudaGetSymbolAddress((void**)&Kp,  g_K);
    cudaGetSymbolAddress((void**)&Vp,  g_V);
    cudaGetSymbolAddress((void**)&AOp, g_AO);

    dim3 ggrid(D_MODEL / 64, (NB * SEQ) / 64);   // (16, 64)
    gemm_bias<<<ggrid, 128>>>(query, Wq, bq, Qp, 1);
    gemm_bias<<<ggrid, 128>>>(key,   Wk, bk, Kp, 1);
    gemm_bias<<<ggrid, 128>>>(value, Wv, bv, Vp, 1);

    dim3 agrid(SEQ / 64, BHS);                   // (32, 32)
    attn_kernel<<<agrid, 128>>>();

    gemm_bias<<<ggrid, 128>>>(AOp, Wo, bo, out, 0);
}

// round 3
// speedup vs baseline: 1.7685x; 1.7685x over previous
#include <cuda_runtime.h>
#include <cuda_bf16.h>
#include <math.h>
#include <stdint.h>

#define D_MODEL 1024
#define K2      2048          // split buffer width: [hi(1024) | lo(1024)]
#define NCHUNK  48            // 3072 logical K / 64 per chunk (hi*hi + lo*hi + hi*lo)
#define SEQ     2048
#define NB      2
#define NH      16
#define HD      64
#define BHS     (NB*NH)
#define M_ROWS  (NB*SEQ)      // 4096

// ---------------- scratch (static device globals) ----------------
__device__ float g_Q[(size_t)BHS * SEQ * HD];
__device__ float g_K[(size_t)BHS * SEQ * HD];
__device__ float g_V[(size_t)BHS * SEQ * HD];
__device__ float g_AO[(size_t)NB * SEQ * D_MODEL];
__device__ __nv_bfloat16 g_Xs[(size_t)M_ROWS * K2];   // activation split (reused)
__device__ __nv_bfloat16 g_Ws[(size_t)D_MODEL * K2];  // weight split (reused)

// ---------------- helpers ----------------
__device__ __forceinline__ uint32_t smem_u32(const void* p) {
    uint32_t a;
    asm("{ .reg .u64 t; cvta.to.shared.u64 t, %1; cvt.u32.u64 %0, t; }" : "=r"(a) : "l"(p));
    return a;
}
#define SWZ128(x) ((x) ^ (((x) >> 3) & 0x70))

#define CPASYNC16(dst, src) \
    asm volatile("cp.async.cg.shared.global [%0], [%1], 16;" :: "r"(dst), "l"(src) : "memory")
#define CPCOMMIT() asm volatile("cp.async.commit_group;" ::: "memory")
#define CPWAIT1()  asm volatile("cp.async.wait_group 1;" ::: "memory")

#define LDSM_X4(r0, r1, r2, r3, addr) \
    asm volatile("ldmatrix.sync.aligned.m8n8.x4.shared.b16 {%0,%1,%2,%3}, [%4];" \
        : "=r"(r0), "=r"(r1), "=r"(r2), "=r"(r3) : "r"(addr))

#define MMA16816(d, a, b0, b1) \
    asm volatile("mma.sync.aligned.m16n8k16.row.col.f32.bf16.bf16.f32 " \
        "{%0,%1,%2,%3}, {%4,%5,%6,%7}, {%8,%9}, {%0,%1,%2,%3};" \
        : "+f"((d)[0]), "+f"((d)[1]), "+f"((d)[2]), "+f"((d)[3]) \
        : "r"((a)[0]), "r"((a)[1]), "r"((a)[2]), "r"((a)[3]), "r"(b0), "r"(b1))

// ---------------- split fp32 -> [hi|lo] bf16 along K ----------------
__global__ __launch_bounds__(256) void split_bf16(const float* __restrict__ x,
                                                  __nv_bfloat16* __restrict__ o,
                                                  int rows)
{
    int idx = blockIdx.x * blockDim.x + threadIdx.x;       // one float4 per thread
    int total = rows * 256;
    if (idx >= total) return;
    int m = idx >> 8;
    int k4 = (idx & 255) * 4;
    float4 v = *(const float4*)(x + (size_t)m * 1024 + k4);
    __nv_bfloat16 h0 = __float2bfloat16(v.x), h1 = __float2bfloat16(v.y);
    __nv_bfloat16 h2 = __float2bfloat16(v.z), h3 = __float2bfloat16(v.w);
    __nv_bfloat16 l0 = __float2bfloat16(v.x - __bfloat162float(h0));
    __nv_bfloat16 l1 = __float2bfloat16(v.y - __bfloat162float(h1));
    __nv_bfloat16 l2 = __float2bfloat16(v.z - __bfloat162float(h2));
    __nv_bfloat16 l3 = __float2bfloat16(v.w - __bfloat162float(h3));
    __nv_bfloat162* ph = (__nv_bfloat162*)(o + (size_t)m * K2 + k4);
    ph[0] = __halves2bfloat162(h0, h1);
    ph[1] = __halves2bfloat162(h2, h3);
    __nv_bfloat162* pl = (__nv_bfloat162*)(o + (size_t)m * K2 + 1024 + k4);
    pl[0] = __halves2bfloat162(l0, l1);
    pl[1] = __halves2bfloat162(l2, l3);
}

// ---------------- HMMA GEMM: out = A'@B'^T + bias ----------------
// Logical A' = [Ahi | Alo | Ahi] (K=3072), B' = [Bhi | Bhi | Blo]:
// product = hi*hi + lo*hi + hi*lo (misses only lo*lo ~ 4e-6 relative).
// 128x128 CTA tile, 256 thr (8 warps = 4Mx2N, warp tile 32x64),
// K-chunk 64 bf16 (128B SW128 rows), 3-stage cp.async pipeline.
#define STAGE_BYTES 32768              // A tile 16KB + B tile 16KB
#define GEMM_SMEM   (3 * STAGE_BYTES)  // 96 KB

__global__ __launch_bounds__(256) void gemm_mma(const __nv_bfloat16* __restrict__ A,
                                                const __nv_bfloat16* __restrict__ B,
                                                const float* __restrict__ bias,
                                                float* __restrict__ out,
                                                int toBHSD)
{
    extern __shared__ char smem[];
    const uint32_t sbase = smem_u32(smem);
    const int tid  = threadIdx.x;
    const int wid  = tid >> 5;
    const int lane = tid & 31;
    const int bm = blockIdx.y * 128;
    const int bn = blockIdx.x * 128;
    const int wm = wid & 3;            // 4 warps along M (32 rows each)
    const int wn = wid >> 2;           // 2 warps along N (64 cols each)

    auto load_chunk = [&](int ic, int st) {
        const int ka = (ic < 32) ? ic * 64 : (ic - 32) * 64;               // A': hi,lo,hi
        const int kb = (ic < 16) ? ic * 64
                     : (ic < 32) ? (ic - 16) * 64
                                 : (ic - 32) * 64 + 1024;                  // B': hi,hi,lo
        const uint32_t dA = sbase + st * STAGE_BYTES;
        const uint32_t dB = dA + 16384;
#pragma unroll
        for (int j = 0; j < 4; j++) {
            int li  = tid + j * 256;          // 0..1023
            int row = li >> 3;
            int cb  = (li & 7) * 16;
            const char* sa = (const char*)A + ((size_t)(bm + row) * K2 + ka) * 2 + cb;
            CPASYNC16(dA + SWZ128(row * 128 + cb), sa);
            const char* sb = (const char*)B + ((size_t)(bn + row) * K2 + kb) * 2 + cb;
            CPASYNC16(dB + SWZ128(row * 128 + cb), sb);
        }
    };

    // fragment address bases (unswizzled tile offsets; +ks*32 then swizzle)
    const int lane8 = lane & 7;
    const int grp   = lane >> 3;
    int aOff[2], bOff[4];
#pragma unroll
    for (int i = 0; i < 2; i++)
        aOff[i] = (wm * 32 + i * 16 + (grp & 1) * 8 + lane8) * 128 + (grp >> 1) * 16;
#pragma unroll
    for (int j = 0; j < 4; j++)
        bOff[j] = (wn * 64 + j * 16 + (grp >> 1) * 8 + lane8) * 128 + (grp & 1) * 16;

    float acc[2][8][4];
#pragma unroll
    for (int i = 0; i < 2; i++)
#pragma unroll
        for (int j = 0; j < 8; j++)
#pragma unroll
            for (int q = 0; q < 4; q++) acc[i][j][q] = 0.f;

    load_chunk(0, 0); CPCOMMIT();
    load_chunk(1, 1); CPCOMMIT();

    for (int ic = 0; ic < NCHUNK; ic++) {
        const int st = ic % 3;
        CPWAIT1();
        __syncthreads();
        const uint32_t sA = sbase + st * STAGE_BYTES;
        const uint32_t sB = sA + 16384;
#pragma unroll
        for (int ks = 0; ks < 4; ks++) {
            uint32_t af[2][4], bf[4][4];
#pragma unroll
            for (int i = 0; i < 2; i++)
                LDSM_X4(af[i][0], af[i][1], af[i][2], af[i][3],
                        sA + SWZ128(aOff[i] + ks * 32));
#pragma unroll
            for (int j = 0; j < 4; j++)
                LDSM_X4(bf[j][0], bf[j][1], bf[j][2], bf[j][3],
                        sB + SWZ128(bOff[j] + ks * 32));
#pragma unroll
            for (int i = 0; i < 2; i++)
#pragma unroll
                for (int j = 0; j < 4; j++) {
                    MMA16816(acc[i][2 * j + 0], af[i], bf[j][0], bf[j][1]);
                    MMA16816(acc[i][2 * j + 1], af[i], bf[j][2], bf[j][3]);
                }
        }
        __syncthreads();
        if (ic + 2 < NCHUNK) load_chunk(ic + 2, (ic + 2) % 3);
        CPCOMMIT();                     // empty group when no load: keeps count uniform
    }

    // epilogue: bias + optional BHSD scatter, float2 stores
    const int r   = lane >> 2;
    const int cp2 = (lane & 3) * 2;
#pragma unroll
    for (int i = 0; i < 2; i++) {
        int m0 = bm + wm * 32 + i * 16 + r;
#pragma unroll
        for (int j = 0; j < 8; j++) {
            int n = bn + wn * 64 + j * 8 + cp2;
            float b0 = bias[n], b1 = bias[n + 1];
            float2 v0 = {acc[i][j][0] + b0, acc[i][j][1] + b1};
            float2 v1 = {acc[i][j][2] + b0, acc[i][j][3] + b1};
            if (toBHSD) {
                int bb = m0 >> 11, h = n >> 6, d = n & (HD - 1);
                int s0 = m0 & (SEQ - 1);
                float* base = out + ((size_t)(bb * NH + h)) * SEQ * HD + d;
                *(float2*)(base + (size_t)s0 * HD)       = v0;
                *(float2*)(base + (size_t)(s0 + 8) * HD) = v1;
            } else {
                *(float2*)(out + (size_t)m0 * D_MODEL + n)       = v0;
                *(float2*)(out + (size_t)(m0 + 8) * D_MODEL + n) = v1;
            }
        }
    }
}

// ---------------------------------------------------------------------------
// Flash attention (fp32 path, unchanged from round 1 — known good)
// ---------------------------------------------------------------------------
__global__ __launch_bounds__(128) void attn_kernel()
{
    __shared__ float Qs[HD][64 + 4];
    __shared__ float Ks[HD][32 + 4];
    __shared__ float Vs[32][HD + 4];
    __shared__ float Ps[32][64 + 4];

    const int bh    = blockIdx.y;
    const int qbase = blockIdx.x * 64;
    const float* Qg = g_Q + (size_t)bh * SEQ * HD;
    const float* Kg = g_K + (size_t)bh * SEQ * HD;
    const float* Vg = g_V + (size_t)bh * SEQ * HD;

    const int tid = threadIdx.x;
    const int tx  = tid & 7;
    const int ty  = tid >> 3;
    const float SCALE = 0.125f;

#pragma unroll
    for (int i = 0; i < 8; i++) {
        int li = tid + i * 128;
        int r  = li >> 4;
        int c4 = (li & 15) * 4;
        float4 v = *(const float4*)(Qg + (size_t)(qbase + r) * HD + c4);
        Qs[c4 + 0][r] = v.x * SCALE; Qs[c4 + 1][r] = v.y * SCALE;
        Qs[c4 + 2][r] = v.z * SCALE; Qs[c4 + 3][r] = v.w * SCALE;
    }

    float o[4][8];
    float m_r[4], l_r[4];
#pragma unroll
    for (int i = 0; i < 4; i++) {
        m_r[i] = -INFINITY; l_r[i] = 0.f;
#pragma unroll
        for (int j = 0; j < 8; j++) o[i][j] = 0.f;
    }

    for (int kt = 0; kt < SEQ; kt += 32) {
        __syncthreads();
#pragma unroll
        for (int i = 0; i < 4; i++) {
            int li = tid + i * 128;
            int r  = li >> 4;
            int c4 = (li & 15) * 4;
            float4 v = *(const float4*)(Kg + (size_t)(kt + r) * HD + c4);
            Ks[c4 + 0][r] = v.x; Ks[c4 + 1][r] = v.y;
            Ks[c4 + 2][r] = v.z; Ks[c4 + 3][r] = v.w;
            float4 w = *(const float4*)(Vg + (size_t)(kt + r) * HD + c4);
            *(float4*)&Vs[r][c4] = w;
        }
        __syncthreads();

        float sc[4][4];
#pragma unroll
        for (int i = 0; i < 4; i++)
#pragma unroll
            for (int j = 0; j < 4; j++) sc[i][j] = 0.f;
#pragma unroll 16
        for (int kk = 0; kk < HD; kk++) {
            float4 a = *(const float4*)&Qs[kk][ty * 4];
            float4 b = *(const float4*)&Ks[kk][tx * 4];
            float av[4] = {a.x, a.y, a.z, a.w};
            float bv[4] = {b.x, b.y, b.z, b.w};
#pragma unroll
            for (int i = 0; i < 4; i++)
#pragma unroll
                for (int j = 0; j < 4; j++)
                    sc[i][j] = fmaf(av[i], bv[j], sc[i][j]);
        }

#pragma unroll
        for (int i = 0; i < 4; i++) {
            float mx = fmaxf(fmaxf(sc[i][0], sc[i][1]), fmaxf(sc[i][2], sc[i][3]));
#pragma unroll
            for (int ofs = 1; ofs < 8; ofs <<= 1)
                mx = fmaxf(mx, __shfl_xor_sync(0xffffffffu, mx, ofs));
            float m_new = fmaxf(m_r[i], mx);
            float p[4], ts = 0.f;
#pragma unroll
            for (int j = 0; j < 4; j++) { p[j] = __expf(sc[i][j] - m_new); ts += p[j]; }
#pragma unroll
            for (int ofs = 1; ofs < 8; ofs <<= 1)
                ts += __shfl_xor_sync(0xffffffffu, ts, ofs);
            float alpha = __expf(m_r[i] - m_new);
            l_r[i] = l_r[i] * alpha + ts;
            m_r[i] = m_new;
            int rr = ty * 4 + i;
#pragma unroll
            for (int j = 0; j < 4; j++) Ps[tx * 4 + j][rr] = p[j];
#pragma unroll
            for (int j = 0; j < 8; j++) o[i][j] *= alpha;
        }
        __syncwarp();

#pragma unroll
        for (int kk = 0; kk < 32; kk++) {
            float4 a  = *(const float4*)&Ps[kk][ty * 4];
            float4 b0 = *(const float4*)&Vs[kk][tx * 8];
            float4 b1 = *(const float4*)&Vs[kk][tx * 8 + 4];
            float av[4] = {a.x, a.y, a.z, a.w};
            float bv[8] = {b0.x, b0.y, b0.z, b0.w, b1.x, b1.y, b1.z, b1.w};
#pragma unroll
            for (int i = 0; i < 4; i++)
#pragma unroll
                for (int j = 0; j < 8; j++)
                    o[i][j] = fmaf(av[i], bv[j], o[i][j]);
        }
    }

    const int b = bh >> 4, h = bh & 15;
#pragma unroll
    for (int i = 0; i < 4; i++) {
        int s = qbase + ty * 4 + i;
        float inv = 1.f / l_r[i];
        float* dst = g_AO + ((size_t)b * SEQ + s) * D_MODEL + h * HD + tx * 8;
#pragma unroll
        for (int j = 0; j < 8; j++) dst[j] = o[i][j] * inv;
    }
}

// ---------------------------------------------------------------------------
extern "C" void kernel_launch(void* const* d_in, const int* in_sizes, int n_in,
                              void* d_out, int out_size)
{
    const float* query = (const float*)d_in[0];
    const float* key   = (const float*)d_in[1];
    const float* value = (const float*)d_in[2];
    const float* Wq    = (const float*)d_in[3];
    const float* bq    = (const float*)d_in[4];
    const float* Wk    = (const float*)d_in[5];
    const float* bk    = (const float*)d_in[6];
    const float* Wv    = (const float*)d_in[7];
    const float* bv    = (const float*)d_in[8];
    const float* Wo    = (const float*)d_in[9];
    const float* bo    = (const float*)d_in[10];
    float* out = (float*)d_out;

    float *Qp, *Kp, *Vp, *AOp;
    __nv_bfloat16 *Xs, *Ws;
    cudaGetSymbolAddress((void**)&Qp,  g_Q);
    cudaGetSymbolAddress((void**)&Kp,  g_K);
    cudaGetSymbolAddress((void**)&Vp,  g_V);
    cudaGetSymbolAddress((void**)&AOp, g_AO);
    cudaGetSymbolAddress((void**)&Xs,  g_Xs);
    cudaGetSymbolAddress((void**)&Ws,  g_Ws);

    cudaFuncSetAttribute(gemm_mma, cudaFuncAttributeMaxDynamicSharedMemorySize, GEMM_SMEM);

    dim3 ggrid(D_MODEL / 128, M_ROWS / 128);          // (8, 32)
    const int sx = M_ROWS;                            // 4096 rows * 256 f4 / 256 thr
    const int sw = D_MODEL;                           // 1024 rows

    // Q projection
    split_bf16<<<sw, 256>>>(Wq, Ws, D_MODEL);
    split_bf16<<<sx, 256>>>(query, Xs, M_ROWS);
    gemm_mma<<<ggrid, 256, GEMM_SMEM>>>(Xs, Ws, bq, Qp, 1);
    // K projection
    split_bf16<<<sw, 256>>>(Wk, Ws, D_MODEL);
    split_bf16<<<sx, 256>>>(key, Xs, M_ROWS);
    gemm_mma<<<ggrid, 256, GEMM_SMEM>>>(Xs, Ws, bk, Kp, 1);
    // V projection
    split_bf16<<<sw, 256>>>(Wv, Ws, D_MODEL);
    split_bf16<<<sx, 256>>>(value, Xs, M_ROWS);
    gemm_mma<<<ggrid, 256, GEMM_SMEM>>>(Xs, Ws, bv, Vp, 1);

    // attention
    dim3 agrid(SEQ / 64, BHS);                        // (32, 32)
    attn_kernel<<<agrid, 128>>>();

    // output projection
    split_bf16<<<sw, 256>>>(Wo, Ws, D_MODEL);
    split_bf16<<<sx, 256>>>(AOp, Xs, M_ROWS);
    gemm_mma<<<ggrid, 256, GEMM_SMEM>>>(Xs, Ws, bo, out, 0);
}

// round 4
// speedup vs baseline: 4.0076x; 2.2661x over previous
#include <cuda_runtime.h>
#include <cuda_bf16.h>
#include <math.h>
#include <stdint.h>

#define D_MODEL 1024
#define K2      2048          // split buffer width: [hi(1024) | lo(1024)]
#define NCHUNK  48            // 3072 logical K (hi*hi + lo*hi + hi*lo)
#define SEQ     2048
#define NB      2
#define NH      16
#define HD      64
#define BHS     (NB*NH)
#define M_ROWS  (NB*SEQ)      // 4096

// ---------------- scratch (static device globals) ----------------
__device__ __nv_bfloat16 g_Qhi[(size_t)BHS * SEQ * HD];
__device__ __nv_bfloat16 g_Qlo[(size_t)BHS * SEQ * HD];
__device__ __nv_bfloat16 g_Khi[(size_t)BHS * SEQ * HD];
__device__ __nv_bfloat16 g_Klo[(size_t)BHS * SEQ * HD];
__device__ __nv_bfloat16 g_Vhi[(size_t)BHS * SEQ * HD];
__device__ __nv_bfloat16 g_Vlo[(size_t)BHS * SEQ * HD];
__device__ float g_AO[(size_t)NB * SEQ * D_MODEL];
__device__ __nv_bfloat16 g_Xs[(size_t)M_ROWS * K2];   // activation split (reused)
__device__ __nv_bfloat16 g_Ws[(size_t)D_MODEL * K2];  // weight split (reused)

// ---------------- helpers ----------------
__device__ __forceinline__ uint32_t smem_u32(const void* p) {
    uint32_t a;
    asm("{ .reg .u64 t; cvta.to.shared.u64 t, %1; cvt.u32.u64 %0, t; }" : "=r"(a) : "l"(p));
    return a;
}
#define SWZ128(x) ((x) ^ (((x) >> 3) & 0x70))

#define CPASYNC16(dst, src) \
    asm volatile("cp.async.cg.shared.global [%0], [%1], 16;" :: "r"(dst), "l"(src) : "memory")
#define CPCOMMIT() asm volatile("cp.async.commit_group;" ::: "memory")
#define CPWAIT1()  asm volatile("cp.async.wait_group 1;" ::: "memory")

#define LDSM_X4(r0, r1, r2, r3, addr) \
    asm volatile("ldmatrix.sync.aligned.m8n8.x4.shared.b16 {%0,%1,%2,%3}, [%4];" \
        : "=r"(r0), "=r"(r1), "=r"(r2), "=r"(r3) : "r"(addr))
#define LDSM_X4T(r0, r1, r2, r3, addr) \
    asm volatile("ldmatrix.sync.aligned.m8n8.x4.trans.shared.b16 {%0,%1,%2,%3}, [%4];" \
        : "=r"(r0), "=r"(r1), "=r"(r2), "=r"(r3) : "r"(addr))

#define MMA16816(d, a, b0, b1) \
    asm volatile("mma.sync.aligned.m16n8k16.row.col.f32.bf16.bf16.f32 " \
        "{%0,%1,%2,%3}, {%4,%5,%6,%7}, {%8,%9}, {%0,%1,%2,%3};" \
        : "+f"((d)[0]), "+f"((d)[1]), "+f"((d)[2]), "+f"((d)[3]) \
        : "r"((a)[0]), "r"((a)[1]), "r"((a)[2]), "r"((a)[3]), "r"(b0), "r"(b1))

// pack two f32 -> bf16x2 (v0 -> low half, v1 -> high half)
__device__ __forceinline__ uint32_t pack_bf2(float v0, float v1) {
    uint32_t r;
    asm("cvt.rn.bf16x2.f32 %0, %1, %2;" : "=r"(r) : "f"(v1), "f"(v0));
    return r;
}
// residuals of a packed pair
__device__ __forceinline__ void resid_bf2(uint32_t h, float v0, float v1,
                                          float& r0, float& r1) {
    r0 = v0 - __uint_as_float(h << 16);
    r1 = v1 - __uint_as_float(h & 0xffff0000u);
}

// ---------------- split fp32 -> [hi|lo] bf16 along K ----------------
__global__ __launch_bounds__(256) void split_bf16(const float* __restrict__ x,
                                                  __nv_bfloat16* __restrict__ o,
                                                  int rows)
{
    int idx = blockIdx.x * blockDim.x + threadIdx.x;       // one float4 per thread
    int total = rows * 256;
    if (idx >= total) return;
    int m = idx >> 8;
    int k4 = (idx & 255) * 4;
    float4 v = *(const float4*)(x + (size_t)m * 1024 + k4);
    uint32_t h0 = pack_bf2(v.x, v.y), h1 = pack_bf2(v.z, v.w);
    float r0, r1, r2, r3;
    resid_bf2(h0, v.x, v.y, r0, r1);
    resid_bf2(h1, v.z, v.w, r2, r3);
    uint32_t* ph = (uint32_t*)(o + (size_t)m * K2 + k4);
    ph[0] = h0; ph[1] = h1;
    uint32_t* pl = (uint32_t*)(o + (size_t)m * K2 + 1024 + k4);
    pl[0] = pack_bf2(r0, r1); pl[1] = pack_bf2(r2, r3);
}

// ---------------- HMMA GEMM: out = A'@B'^T + bias ----------------
// A' = [Ahi | Alo | Ahi] (K=3072), B' = [Bhi | Bhi | Blo].
// mode 0: fp32 out[m][1024]; mode 1: Q (scale 0.125, split hi/lo BHSD);
// mode 2: K/V (split hi/lo BHSD).
#define STAGE_BYTES 32768
#define GEMM_SMEM   (3 * STAGE_BYTES)

__global__ __launch_bounds__(256) void gemm_mma(const __nv_bfloat16* __restrict__ A,
                                                const __nv_bfloat16* __restrict__ B,
                                                const float* __restrict__ bias,
                                                float* __restrict__ outF,
                                                __nv_bfloat16* __restrict__ outHi,
                                                __nv_bfloat16* __restrict__ outLo,
                                                int mode)
{
    extern __shared__ char smem[];
    const uint32_t sbase = smem_u32(smem);
    const int tid  = threadIdx.x;
    const int wid  = tid >> 5;
    const int lane = tid & 31;
    const int bm = blockIdx.y * 128;
    const int bn = blockIdx.x * 128;
    const int wm = wid & 3;
    const int wn = wid >> 2;

    auto load_chunk = [&](int ic, int st) {
        const int ka = (ic < 32) ? ic * 64 : (ic - 32) * 64;
        const int kb = (ic < 16) ? ic * 64
                     : (ic < 32) ? (ic - 16) * 64
                                 : (ic - 32) * 64 + 1024;
        const uint32_t dA = sbase + st * STAGE_BYTES;
        const uint32_t dB = dA + 16384;
#pragma unroll
        for (int j = 0; j < 4; j++) {
            int li  = tid + j * 256;
            int row = li >> 3;
            int cb  = (li & 7) * 16;
            const char* sa = (const char*)A + ((size_t)(bm + row) * K2 + ka) * 2 + cb;
            CPASYNC16(dA + SWZ128(row * 128 + cb), sa);
            const char* sb = (const char*)B + ((size_t)(bn + row) * K2 + kb) * 2 + cb;
            CPASYNC16(dB + SWZ128(row * 128 + cb), sb);
        }
    };

    const int lane8 = lane & 7;
    const int grp   = lane >> 3;
    int aOff[2], bOff[4];
#pragma unroll
    for (int i = 0; i < 2; i++)
        aOff[i] = (wm * 32 + i * 16 + (grp & 1) * 8 + lane8) * 128 + (grp >> 1) * 16;
#pragma unroll
    for (int j = 0; j < 4; j++)
        bOff[j] = (wn * 64 + j * 16 + (grp >> 1) * 8 + lane8) * 128 + (grp & 1) * 16;

    float acc[2][8][4];
#pragma unroll
    for (int i = 0; i < 2; i++)
#pragma unroll
        for (int j = 0; j < 8; j++)
#pragma unroll
            for (int q = 0; q < 4; q++) acc[i][j][q] = 0.f;

    load_chunk(0, 0); CPCOMMIT();
    load_chunk(1, 1); CPCOMMIT();

    for (int ic = 0; ic < NCHUNK; ic++) {
        const int st = ic % 3;
        CPWAIT1();
        __syncthreads();
        const uint32_t sA = sbase + st * STAGE_BYTES;
        const uint32_t sB = sA + 16384;
#pragma unroll
        for (int ks = 0; ks < 4; ks++) {
            uint32_t af[2][4], bf[4][4];
#pragma unroll
            for (int i = 0; i < 2; i++)
                LDSM_X4(af[i][0], af[i][1], af[i][2], af[i][3],
                        sA + SWZ128(aOff[i] + ks * 32));
#pragma unroll
            for (int j = 0; j < 4; j++)
                LDSM_X4(bf[j][0], bf[j][1], bf[j][2], bf[j][3],
                        sB + SWZ128(bOff[j] + ks * 32));
#pragma unroll
            for (int i = 0; i < 2; i++)
#pragma unroll
                for (int j = 0; j < 4; j++) {
                    MMA16816(acc[i][2 * j + 0], af[i], bf[j][0], bf[j][1]);
                    MMA16816(acc[i][2 * j + 1], af[i], bf[j][2], bf[j][3]);
                }
        }
        __syncthreads();
        if (ic + 2 < NCHUNK) load_chunk(ic + 2, (ic + 2) % 3);
        CPCOMMIT();
    }

    const int r   = lane >> 2;
    const int cp2 = (lane & 3) * 2;
    const float scl = (mode == 1) ? 0.125f : 1.f;
#pragma unroll
    for (int i = 0; i < 2; i++) {
        int m0 = bm + wm * 32 + i * 16 + r;
#pragma unroll
        for (int j = 0; j < 8; j++) {
            int n = bn + wn * 64 + j * 8 + cp2;
            float b0 = bias[n], b1 = bias[n + 1];
            float v0 = acc[i][j][0] + b0, v1 = acc[i][j][1] + b1;
            float v2 = acc[i][j][2] + b0, v3 = acc[i][j][3] + b1;
            if (mode == 0) {
                *(float2*)(outF + (size_t)m0 * D_MODEL + n)       = make_float2(v0, v1);
                *(float2*)(outF + (size_t)(m0 + 8) * D_MODEL + n) = make_float2(v2, v3);
            } else {
                v0 *= scl; v1 *= scl; v2 *= scl; v3 *= scl;
                int bb = m0 >> 11, h = n >> 6, d = n & (HD - 1);
                int s0 = m0 & (SEQ - 1);
                size_t base = ((size_t)(bb * NH + h) * SEQ + s0) * HD + d;
                uint32_t h0 = pack_bf2(v0, v1);
                float r0, r1; resid_bf2(h0, v0, v1, r0, r1);
                *(uint32_t*)(outHi + base) = h0;
                *(uint32_t*)(outLo + base) = pack_bf2(r0, r1);
                uint32_t h1 = pack_bf2(v2, v3);
                float r2, r3; resid_bf2(h1, v2, v3, r2, r3);
                *(uint32_t*)(outHi + base + 8 * HD) = h1;
                *(uint32_t*)(outLo + base + 8 * HD) = pack_bf2(r2, r3);
            }
        }
    }
}

// ---------------------------------------------------------------------------
// HMMA flash attention: CTA = 128 queries x full head; stream 128-key tiles.
// S = Qhi*Khi + Qlo*Khi + Qhi*Klo ; O += Phi*Vhi + Plo*Vhi + Phi*Vlo.
// 256 thr, 8 warps x 16 q-rows. 2-stage cp.async pipeline for K/V hi/lo.
// ---------------------------------------------------------------------------
#define SQ_HI   0
#define SQ_LO   16384
#define SKV     32768
#define KVSTAGE 65536                   // Khi|Klo|Vhi|Vlo (16KB each)
#define ATTN_SMEM (SKV + 2 * KVSTAGE)   // 160 KB

__global__ __launch_bounds__(256) void attn_mma()
{
    extern __shared__ char smem[];
    const uint32_t sbase = smem_u32(smem);
    const int tid  = threadIdx.x;
    const int wid  = tid >> 5;
    const int lane = tid & 31;
    const int bh    = blockIdx.y;
    const int qbase = blockIdx.x * 128;
    const size_t qoff = ((size_t)bh * SEQ + qbase) * HD;

    // ---- load Q (hi+lo) ----
    {
        const char* qh = (const char*)(g_Qhi) + qoff * 2;
        const char* ql = (const char*)(g_Qlo) + qoff * 2;
#pragma unroll
        for (int j = 0; j < 4; j++) {
            int li = tid + j * 256;
            int row = li >> 3;
            int cb  = (li & 7) * 16;
            uint32_t so = SWZ128(row * 128 + cb);
            CPASYNC16(sbase + SQ_HI + so, qh + row * 128 + cb);
            CPASYNC16(sbase + SQ_LO + so, ql + row * 128 + cb);
        }
    }
    auto load_kv = [&](int kt, int st) {
        const size_t go = ((size_t)bh * SEQ + kt * 128) * HD * 2;
        const uint32_t base = sbase + SKV + st * KVSTAGE;
#pragma unroll
        for (int j = 0; j < 4; j++) {
            int li = tid + j * 256;
            int row = li >> 3;
            int cb  = (li & 7) * 16;
            uint32_t so = SWZ128(row * 128 + cb);
            size_t g = go + row * 128 + cb;
            CPASYNC16(base + so,         (const char*)g_Khi + g);
            CPASYNC16(base + 16384 + so, (const char*)g_Klo + g);
            CPASYNC16(base + 32768 + so, (const char*)g_Vhi + g);
            CPASYNC16(base + 49152 + so, (const char*)g_Vlo + g);
        }
    };
    load_kv(0, 0); CPCOMMIT();
    load_kv(1, 1); CPCOMMIT();

    const int lane8 = lane & 7;
    const int grp   = lane >> 3;
    // A (Q) ldsm offset: rows wid*16.., col segment by grp
    const int aOff  = (wid * 16 + (grp & 1) * 8 + lane8) * 128 + (grp >> 1) * 16;
    // B (K) ldsm offset pieces
    const int bRowC = (grp >> 1) * 8 + lane8;
    const int bColB = (grp & 1) * 16;
    // V trans ldsm pieces
    const int vRowC = (grp & 1) * 8 + lane8;
    const int vColB = (grp >> 1) * 16;

    float o[8][4];
#pragma unroll
    for (int j = 0; j < 8; j++)
#pragma unroll
        for (int q = 0; q < 4; q++) o[j][q] = 0.f;
    float m0 = -INFINITY, m1 = -INFINITY, l0 = 0.f, l1 = 0.f;

    for (int kt = 0; kt < 16; kt++) {
        CPWAIT1();
        __syncthreads();
        const uint32_t kv = sbase + SKV + (kt & 1) * KVSTAGE;

        // ---- S = Q K^T (3 terms) ----
        float sc[16][4];
#pragma unroll
        for (int t = 0; t < 16; t++)
#pragma unroll
            for (int q = 0; q < 4; q++) sc[t][q] = 0.f;

#pragma unroll
        for (int term = 0; term < 3; term++) {
            const uint32_t aB = sbase + ((term == 1) ? SQ_LO : SQ_HI);
            const uint32_t bB = kv + ((term == 2) ? 16384 : 0);
#pragma unroll
            for (int ks = 0; ks < 4; ks++) {
                uint32_t af[4];
                LDSM_X4(af[0], af[1], af[2], af[3], aB + SWZ128(aOff + ks * 32));
#pragma unroll
                for (int j = 0; j < 8; j++) {
                    uint32_t bf[4];
                    LDSM_X4(bf[0], bf[1], bf[2], bf[3],
                            bB + SWZ128((j * 16 + bRowC) * 128 + bColB + ks * 32));
                    MMA16816(sc[2 * j + 0], af, bf[0], bf[1]);
                    MMA16816(sc[2 * j + 1], af, bf[2], bf[3]);
                }
            }
        }

        // ---- online softmax on fragments ----
        float mx0 = sc[0][0], mx1 = sc[0][2];
#pragma unroll
        for (int t = 0; t < 16; t++) {
            mx0 = fmaxf(mx0, fmaxf(sc[t][0], sc[t][1]));
            mx1 = fmaxf(mx1, fmaxf(sc[t][2], sc[t][3]));
        }
        mx0 = fmaxf(mx0, __shfl_xor_sync(0xffffffffu, mx0, 1));
        mx0 = fmaxf(mx0, __shfl_xor_sync(0xffffffffu, mx0, 2));
        mx1 = fmaxf(mx1, __shfl_xor_sync(0xffffffffu, mx1, 1));
        mx1 = fmaxf(mx1, __shfl_xor_sync(0xffffffffu, mx1, 2));
        float mn0 = fmaxf(m0, mx0), mn1 = fmaxf(m1, mx1);
        float a0 = __expf(m0 - mn0), a1 = __expf(m1 - mn1);
        m0 = mn0; m1 = mn1;
        float s0 = 0.f, s1 = 0.f;
#pragma unroll
        for (int t = 0; t < 16; t++) {
            sc[t][0] = __expf(sc[t][0] - mn0);
            sc[t][1] = __expf(sc[t][1] - mn0);
            sc[t][2] = __expf(sc[t][2] - mn1);
            sc[t][3] = __expf(sc[t][3] - mn1);
            s0 += sc[t][0] + sc[t][1];
            s1 += sc[t][2] + sc[t][3];
        }
        s0 += __shfl_xor_sync(0xffffffffu, s0, 1);
        s0 += __shfl_xor_sync(0xffffffffu, s0, 2);
        s1 += __shfl_xor_sync(0xffffffffu, s1, 1);
        s1 += __shfl_xor_sync(0xffffffffu, s1, 2);
        l0 = l0 * a0 + s0;
        l1 = l1 * a1 + s1;
#pragma unroll
        for (int j = 0; j < 8; j++) {
            o[j][0] *= a0; o[j][1] *= a0;
            o[j][2] *= a1; o[j][3] *= a1;
        }

        // ---- O += P V (3 terms) ----
#pragma unroll
        for (int kk = 0; kk < 8; kk++) {
            uint32_t ph[4], pl[4];
            float r0, r1;
            ph[0] = pack_bf2(sc[2*kk][0],   sc[2*kk][1]);
            resid_bf2(ph[0], sc[2*kk][0], sc[2*kk][1], r0, r1);   pl[0] = pack_bf2(r0, r1);
            ph[1] = pack_bf2(sc[2*kk][2],   sc[2*kk][3]);
            resid_bf2(ph[1], sc[2*kk][2], sc[2*kk][3], r0, r1);   pl[1] = pack_bf2(r0, r1);
            ph[2] = pack_bf2(sc[2*kk+1][0], sc[2*kk+1][1]);
            resid_bf2(ph[2], sc[2*kk+1][0], sc[2*kk+1][1], r0, r1); pl[2] = pack_bf2(r0, r1);
            ph[3] = pack_bf2(sc[2*kk+1][2], sc[2*kk+1][3]);
            resid_bf2(ph[3], sc[2*kk+1][2], sc[2*kk+1][3], r0, r1); pl[3] = pack_bf2(r0, r1);
#pragma unroll
            for (int j = 0; j < 4; j++) {
                uint32_t vh[4], vl[4];
                uint32_t vaddr = SWZ128((kk * 16 + vRowC) * 128 + j * 32 + vColB);
                LDSM_X4T(vh[0], vh[1], vh[2], vh[3], kv + 32768 + vaddr);
                LDSM_X4T(vl[0], vl[1], vl[2], vl[3], kv + 49152 + vaddr);
                MMA16816(o[2*j + 0], ph, vh[0], vh[1]);
                MMA16816(o[2*j + 1], ph, vh[2], vh[3]);
                MMA16816(o[2*j + 0], pl, vh[0], vh[1]);
                MMA16816(o[2*j + 1], pl, vh[2], vh[3]);
                MMA16816(o[2*j + 0], ph, vl[0], vl[1]);
                MMA16816(o[2*j + 1], ph, vl[2], vl[3]);
            }
        }

        __syncthreads();
        if (kt + 2 < 16) load_kv(kt + 2, kt & 1);
        CPCOMMIT();
    }

    // ---- epilogue: normalize, write (B,S,H*Hd) fp32 for O-projection ----
    const int b = bh >> 4, h = bh & 15;
    const int srow = qbase + wid * 16 + (lane >> 2);
    const int cp2  = (lane & 3) * 2;
    const float i0 = 1.f / l0, i1 = 1.f / l1;
    float* d0 = g_AO + ((size_t)b * SEQ + srow) * D_MODEL + h * HD + cp2;
    float* d1 = g_AO + ((size_t)b * SEQ + srow + 8) * D_MODEL + h * HD + cp2;
#pragma unroll
    for (int j = 0; j < 8; j++) {
        *(float2*)(d0 + j * 8) = make_float2(o[j][0] * i0, o[j][1] * i0);
        *(float2*)(d1 + j * 8) = make_float2(o[j][2] * i1, o[j][3] * i1);
    }
}

// ---------------------------------------------------------------------------
extern "C" void kernel_launch(void* const* d_in, const int* in_sizes, int n_in,
                              void* d_out, int out_size)
{
    const float* query = (const float*)d_in[0];
    const float* key   = (const float*)d_in[1];
    const float* value = (const float*)d_in[2];
    const float* Wq    = (const float*)d_in[3];
    const float* bq    = (const float*)d_in[4];
    const float* Wk    = (const float*)d_in[5];
    const float* bk    = (const float*)d_in[6];
    const float* Wv    = (const float*)d_in[7];
    const float* bv    = (const float*)d_in[8];
    const float* Wo    = (const float*)d_in[9];
    const float* bo    = (const float*)d_in[10];
    float* out = (float*)d_out;

    float* AOp;
    __nv_bfloat16 *Xs, *Ws, *qhi, *qlo, *khi, *klo, *vhi, *vlo;
    cudaGetSymbolAddress((void**)&AOp, g_AO);
    cudaGetSymbolAddress((void**)&Xs,  g_Xs);
    cudaGetSymbolAddress((void**)&Ws,  g_Ws);
    cudaGetSymbolAddress((void**)&qhi, g_Qhi);
    cudaGetSymbolAddress((void**)&qlo, g_Qlo);
    cudaGetSymbolAddress((void**)&khi, g_Khi);
    cudaGetSymbolAddress((void**)&klo, g_Klo);
    cudaGetSymbolAddress((void**)&vhi, g_Vhi);
    cudaGetSymbolAddress((void**)&vlo, g_Vlo);

    cudaFuncSetAttribute(gemm_mma, cudaFuncAttributeMaxDynamicSharedMemorySize, GEMM_SMEM);
    cudaFuncSetAttribute(attn_mma, cudaFuncAttributeMaxDynamicSharedMemorySize, ATTN_SMEM);

    dim3 ggrid(D_MODEL / 128, M_ROWS / 128);          // (8, 32)
    const int sx = M_ROWS;
    const int sw = D_MODEL;

    // Q projection (scaled + split)
    split_bf16<<<sw, 256>>>(Wq, Ws, D_MODEL);
    split_bf16<<<sx, 256>>>(query, Xs, M_ROWS);
    gemm_mma<<<ggrid, 256, GEMM_SMEM>>>(Xs, Ws, bq, nullptr, qhi, qlo, 1);
    // K projection (split)
    split_bf16<<<sw, 256>>>(Wk, Ws, D_MODEL);
    split_bf16<<<sx, 256>>>(key, Xs, M_ROWS);
    gemm_mma<<<ggrid, 256, GEMM_SMEM>>>(Xs, Ws, bk, nullptr, khi, klo, 2);
    // V projection (split)
    split_bf16<<<sw, 256>>>(Wv, Ws, D_MODEL);
    split_bf16<<<sx, 256>>>(value, Xs, M_ROWS);
    gemm_mma<<<ggrid, 256, GEMM_SMEM>>>(Xs, Ws, bv, nullptr, vhi, vlo, 2);

    // attention (HMMA)
    dim3 agrid(SEQ / 128, BHS);                       // (16, 32)
    attn_mma<<<agrid, 256, ATTN_SMEM>>>();

    // output projection (fp32 out)
    split_bf16<<<sw, 256>>>(Wo, Ws, D_MODEL);
    split_bf16<<<sx, 256>>>(AOp, Xs, M_ROWS);
    gemm_mma<<<ggrid, 256, GEMM_SMEM>>>(Xs, Ws, bo, out, nullptr, nullptr, 0);
}